// round 1
// baseline (speedup 1.0000x reference)
#include <cuda_runtime.h>

#define Bv 2
#define CINv 64
#define COUTv 64
#define Hv 192
#define Wv 192
#define Gv 2
#define KKv 9
#define CGv 32
#define HWv (Hv*Wv)

// ---------------- scratch (__device__ globals; no runtime alloc) ----------------
__device__ float g_nhwc[Bv*Hv*Wv*CINv];        // input transposed to NHWC
__device__ float g_py  [Bv*Gv*KKv*HWv];        // absolute sample y
__device__ float g_px  [Bv*Gv*KKv*HWv];        // absolute sample x
__device__ float g_dm  [Bv*Gv*KKv*HWv];        // modulation mask (post-sigmoid)
__device__ float g_wt  [Gv*KKv*CGv*COUTv];     // main weight transposed [g][k][c][o]
__device__ float g_wk  [KKv*64*28];            // sem+m2 weights transposed [k][c][oc(28)]

// ---------------- f32x2 packed helpers ----------------
__device__ __forceinline__ unsigned long long pack2(float lo, float hi) {
    unsigned long long r;
    asm("mov.b64 %0, {%1, %2};" : "=l"(r) : "f"(lo), "f"(hi));
    return r;
}
__device__ __forceinline__ void ffma2(unsigned long long &d,
                                      unsigned long long a,
                                      unsigned long long b) {
    asm("fma.rn.f32x2 %0, %1, %2, %0;" : "+l"(d) : "l"(a), "l"(b));
}
__device__ __forceinline__ float2 unpack2(unsigned long long v) {
    float2 r;
    asm("mov.b64 {%0, %1}, %2;" : "=f"(r.x), "=f"(r.y) : "l"(v));
    return r;
}

// ---------------- kernel: NCHW -> NHWC transpose (smem tiled) ----------------
__global__ void k_transpose(const float* __restrict__ in) {
    __shared__ float tile[64][33];
    int b  = blockIdx.z;
    int h  = blockIdx.y;
    int w0 = blockIdx.x * 32;
    int tw = threadIdx.x & 31;       // 0..31 (w within tile)
    int tc = threadIdx.x >> 5;       // 0..7
    #pragma unroll
    for (int c = tc; c < 64; c += 8)
        tile[c][tw] = in[(((size_t)b*CINv + c)*Hv + h)*Wv + w0 + tw];
    __syncthreads();
    int oc = threadIdx.x & 63;
    #pragma unroll
    for (int j = threadIdx.x >> 6; j < 32; j += 4)
        g_nhwc[(((size_t)b*Hv + h)*Wv + w0 + j)*CINv + oc] = tile[oc][j];
}

// ---------------- kernel: transpose weights into gather-friendly layouts ----------------
__global__ void k_prep(const float* __restrict__ weight,
                       const float* __restrict__ sem_w,
                       const float* __restrict__ m2_w) {
    int i = blockIdx.x * 256 + threadIdx.x;   // covers 36864 = Gv*KKv*CGv*COUTv
    if (i < Gv*KKv*CGv*COUTv) {
        int o = i & 63;
        int c = (i >> 6) & 31;
        int k = (i >> 11) % KKv;
        int g = i / (2048 * KKv);
        // weight layout: [o][cin=g*32+c][k]
        g_wt[i] = weight[((size_t)o*CINv + g*CGv + c)*KKv + k];
    }
    if (i < KKv*64*28) {
        int oc = i % 28;
        int c  = (i / 28) % 64;
        int k  = i / (28 * 64);
        float v = 0.f;
        if (oc < 18)      v = sem_w[((size_t)oc*64 + c)*KKv + k];
        else if (oc < 27) v = m2_w[((size_t)(oc-18)*64 + c)*KKv + k];
        g_wk[i] = v;
    }
}

// ---------------- kernel: offsets + modulation masks + update_mask ----------------
// one thread = one pixel. Fused: sem conv (18 ch) + m2 conv (9 ch) via f32x2,
// reg conv (18 ch) + m1 conv (9 ch) from 1-ch mask, bilinear mask gather for update_mask.
__global__ void __launch_bounds__(128)
k_offsets(const float* __restrict__ mask,
          const float* __restrict__ sem_b,
          const float* __restrict__ reg_w, const float* __restrict__ reg_b,
          const float* __restrict__ m1_w,  const float* __restrict__ m1_b,
          const float* __restrict__ m2_b,
          float* __restrict__ out) {
    extern __shared__ float wsm[];   // [k][c][28] = 16128 floats
    for (int i = threadIdx.x * 4; i < KKv*64*28; i += 128 * 4)
        *(float4*)(wsm + i) = *(const float4*)(g_wk + i);
    __syncthreads();

    int pix = blockIdx.x * 128 + threadIdx.x;
    int b  = pix / HWv;
    int hw = pix % HWv;
    int h  = hw / Wv;
    int w  = hw % Wv;

    // 28 accumulators packed as 14 f32x2 (0..17 sem offsets, 18..26 m2 logits, 27 pad)
    unsigned long long acc[14];
    #pragma unroll
    for (int j = 0; j < 14; j++) {
        int a = 2*j, c2 = 2*j + 1;
        float lo = (a  < 18) ? sem_b[a]       : ((a  < 27) ? m2_b[a  - 18] : 0.f);
        float hi = (c2 < 18) ? sem_b[c2]      : ((c2 < 27) ? m2_b[c2 - 18] : 0.f);
        acc[j] = pack2(lo, hi);
    }

    #pragma unroll 1
    for (int k = 0; k < 9; k++) {
        int yy = h + k / 3 - 1, xx = w + k % 3 - 1;
        if ((unsigned)yy < Hv && (unsigned)xx < Wv) {
            const float4* p = (const float4*)(g_nhwc + (((size_t)b*Hv + yy)*Wv + xx)*64);
            const float* wrow = wsm + k * 64 * 28;
            #pragma unroll 2
            for (int c4 = 0; c4 < 16; c4++) {
                float4 v = p[c4];
                float sarr[4] = {v.x, v.y, v.z, v.w};
                #pragma unroll
                for (int e = 0; e < 4; e++) {
                    unsigned long long s2 = pack2(sarr[e], sarr[e]);
                    const ulonglong2* wp = (const ulonglong2*)(wrow + (c4*4 + e) * 28);
                    #pragma unroll
                    for (int j2 = 0; j2 < 7; j2++) {
                        ulonglong2 q = wp[j2];
                        ffma2(acc[2*j2],     s2, q.x);
                        ffma2(acc[2*j2 + 1], s2, q.y);
                    }
                }
            }
        }
    }
    float res[28];
    #pragma unroll
    for (int j = 0; j < 14; j++) { float2 t = unpack2(acc[j]); res[2*j] = t.x; res[2*j+1] = t.y; }

    // reg (18) and m1 (9) convs from the 1-channel mask
    float mv[9];
    #pragma unroll
    for (int k = 0; k < 9; k++) {
        int yy = h + k / 3 - 1, xx = w + k % 3 - 1;
        mv[k] = ((unsigned)yy < Hv && (unsigned)xx < Wv) ? mask[(size_t)b*HWv + yy*Wv + xx] : 0.f;
    }
    float ro[18];
    #pragma unroll
    for (int i = 0; i < 18; i++) {
        float s = reg_b[i];
        #pragma unroll
        for (int k = 0; k < 9; k++) s += mv[k] * __ldg(&reg_w[i*9 + k]);
        ro[i] = s;
    }
    float d1[9];
    #pragma unroll
    for (int j = 0; j < 9; j++) {
        float s = m1_b[j];
        #pragma unroll
        for (int k = 0; k < 9; k++) s += mv[k] * __ldg(&m1_w[j*9 + k]);
        d1[j] = 1.f / (1.f + __expf(-s));
    }

    const float* mb = mask + (size_t)b * HWv;
    float umsum = 0.f;
    #pragma unroll
    for (int g = 0; g < 2; g++) {
        #pragma unroll
        for (int k = 0; k < 9; k++) {
            float dy = g ? res[2*k]     : ro[2*k];
            float dx = g ? res[2*k + 1] : ro[2*k + 1];
            float py = dy + (float)h + (float)(k / 3 - 1);
            float px = dx + (float)w + (float)(k % 3 - 1);
            int idx = (((b*2 + g)*9) + k) * HWv + hw;
            g_py[idx] = py;
            g_px[idx] = px;
            g_dm[idx] = g ? (1.f / (1.f + __expf(-res[18 + k]))) : d1[k];

            float y0f = floorf(py), x0f = floorf(px);
            int y0 = (int)y0f, x0 = (int)x0f;
            float ly = py - y0f, lx = px - x0f;
            float v00 = ((unsigned)y0     < Hv && (unsigned)x0     < Wv) ? mb[y0*Wv + x0]         : 0.f;
            float v01 = ((unsigned)y0     < Hv && (unsigned)(x0+1) < Wv) ? mb[y0*Wv + x0 + 1]     : 0.f;
            float v10 = ((unsigned)(y0+1) < Hv && (unsigned)x0     < Wv) ? mb[(y0+1)*Wv + x0]     : 0.f;
            float v11 = ((unsigned)(y0+1) < Hv && (unsigned)(x0+1) < Wv) ? mb[(y0+1)*Wv + x0 + 1] : 0.f;
            umsum += (v00*(1.f-ly) + v10*ly)*(1.f-lx) + (v01*(1.f-ly) + v11*ly)*lx;
        }
    }
    // update_mask = clip(2*CG * sum, 0, 1); written into the tail of d_out
    out[(size_t)Bv*COUTv*HWv + (size_t)b*HWv + hw] = fminf(fmaxf(64.f * umsum, 0.f), 1.f);
}

// ---------------- kernel: main modulated deformable conv ----------------
// one thread = one pixel; 64 fp32 accumulators packed into 32 f32x2 regs.
// Weights for the current group staged in SMEM (72KB -> 3 blocks/SM).
__global__ void __launch_bounds__(128)
k_main(const float* __restrict__ bias, float* __restrict__ out) {
    extern __shared__ float wsm[];   // [k][c][o] for current g = 18432 floats

    int pix = blockIdx.x * 128 + threadIdx.x;
    int b  = pix / HWv;
    int hw = pix % HWv;

    unsigned long long acc[32];
    #pragma unroll
    for (int j = 0; j < 32; j++) acc[j] = pack2(bias[2*j], bias[2*j + 1]);

    float um = out[(size_t)Bv*COUTv*HWv + (size_t)b*HWv + hw];

    #pragma unroll 1
    for (int g = 0; g < 2; g++) {
        __syncthreads();
        for (int i = threadIdx.x * 4; i < Gv*KKv*CGv*COUTv/2; i += 128 * 4)
            *(float4*)(wsm + i) = *(const float4*)(g_wt + g * (KKv*CGv*COUTv) + i);
        __syncthreads();

        #pragma unroll 1
        for (int k = 0; k < 9; k++) {
            int idx = (((b*2 + g)*9) + k) * HWv + hw;
            float py = g_py[idx], px = g_px[idx], dm = g_dm[idx];
            float y0f = floorf(py), x0f = floorf(px);
            int y0 = (int)y0f, x0 = (int)x0f;
            float ly = py - y0f, lx = px - x0f;
            bool vy0 = (unsigned)y0       < Hv;
            bool vy1 = (unsigned)(y0 + 1) < Hv;
            bool vx0 = (unsigned)x0       < Wv;
            bool vx1 = (unsigned)(x0 + 1) < Wv;
            float w00 = (vy0 && vx0) ? (1.f-ly)*(1.f-lx)*dm : 0.f;
            float w01 = (vy0 && vx1) ? (1.f-ly)*lx*dm       : 0.f;
            float w10 = (vy1 && vx0) ? ly*(1.f-lx)*dm       : 0.f;
            float w11 = (vy1 && vx1) ? ly*lx*dm             : 0.f;
            int yc0 = min(max(y0, 0), Hv-1),   yc1 = min(max(y0+1, 0), Hv-1);
            int xc0 = min(max(x0, 0), Wv-1),   xc1 = min(max(x0+1, 0), Wv-1);
            const float4* p00 = (const float4*)(g_nhwc + (((size_t)b*Hv + yc0)*Wv + xc0)*64 + g*32);
            const float4* p01 = (const float4*)(g_nhwc + (((size_t)b*Hv + yc0)*Wv + xc1)*64 + g*32);
            const float4* p10 = (const float4*)(g_nhwc + (((size_t)b*Hv + yc1)*Wv + xc0)*64 + g*32);
            const float4* p11 = (const float4*)(g_nhwc + (((size_t)b*Hv + yc1)*Wv + xc1)*64 + g*32);
            const float* wbase = wsm + k * 32 * 64;

            #pragma unroll 2
            for (int c4 = 0; c4 < 8; c4++) {
                float4 a00 = p00[c4], a01 = p01[c4], a10 = p10[c4], a11 = p11[c4];
                float sarr[4];
                sarr[0] = w00*a00.x + w01*a01.x + w10*a10.x + w11*a11.x;
                sarr[1] = w00*a00.y + w01*a01.y + w10*a10.y + w11*a11.y;
                sarr[2] = w00*a00.z + w01*a01.z + w10*a10.z + w11*a11.z;
                sarr[3] = w00*a00.w + w01*a01.w + w10*a10.w + w11*a11.w;
                #pragma unroll
                for (int e = 0; e < 4; e++) {
                    unsigned long long s2 = pack2(sarr[e], sarr[e]);
                    const ulonglong2* wp = (const ulonglong2*)(wbase + (c4*4 + e) * 64);
                    #pragma unroll
                    for (int j2 = 0; j2 < 16; j2++) {
                        ulonglong2 q = wp[j2];
                        ffma2(acc[2*j2],     s2, q.x);
                        ffma2(acc[2*j2 + 1], s2, q.y);
                    }
                }
            }
        }
    }

    #pragma unroll
    for (int j = 0; j < 32; j++) {
        float2 t = unpack2(acc[j]);
        out[((size_t)b*COUTv + 2*j)     * HWv + hw] = t.x * um;
        out[((size_t)b*COUTv + 2*j + 1) * HWv + hw] = t.y * um;
    }
}

// ---------------- launcher ----------------
extern "C" void kernel_launch(void* const* d_in, const int* in_sizes, int n_in,
                              void* d_out, int out_size) {
    const float* input  = (const float*)d_in[0];
    const float* mask   = (const float*)d_in[1];
    const float* weight = (const float*)d_in[2];
    const float* bias   = (const float*)d_in[3];
    const float* sem_w  = (const float*)d_in[4];
    const float* sem_b  = (const float*)d_in[5];
    const float* reg_w  = (const float*)d_in[6];
    const float* reg_b  = (const float*)d_in[7];
    const float* m1_w   = (const float*)d_in[8];
    const float* m1_b   = (const float*)d_in[9];
    const float* m2_w   = (const float*)d_in[10];
    const float* m2_b   = (const float*)d_in[11];
    float* out = (float*)d_out;

    // idempotent, deterministic attribute sets (dynamic smem > 48KB)
    cudaFuncSetAttribute(k_offsets, cudaFuncAttributeMaxDynamicSharedMemorySize, KKv*64*28*4);
    cudaFuncSetAttribute(k_main,    cudaFuncAttributeMaxDynamicSharedMemorySize, KKv*CGv*COUTv*4);

    k_transpose<<<dim3(Wv/32, Hv, Bv), 256>>>(input);
    k_prep<<<(Gv*KKv*CGv*COUTv + 255)/256, 256>>>(weight, sem_w, m2_w);
    k_offsets<<<(Bv*HWv)/128, 128, KKv*64*28*4>>>(mask, sem_b, reg_w, reg_b,
                                                  m1_w, m1_b, m2_b, out);
    k_main<<<(Bv*HWv)/128, 128, KKv*CGv*COUTv*4>>>(bias, out);
}